// round 3
// baseline (speedup 1.0000x reference)
#include <cuda_runtime.h>
#include <cuda_bf16.h>
#include <cstdint>

// ---------------------------------------------------------------------------
// EdgeAlignmentModule: hash-join of new edges against old edges.
//   key(src,dst) = src * total_nodes + dst   (fits in int32: < 1e8)
//   For each new edge: if key existed among old edges, gather
//   [edge_attr_old(3), flow_old(1)] of the matching old edge (MAX old index
//   wins on duplicate keys, matching sequential scatter semantics of
//   table.at[old_keys].set(arange)), else zeros. Append edge_attr_new(3)
//   and is_new_edge flag.
// ---------------------------------------------------------------------------

#define TABLE_LOG2 21
#define TABLE_SIZE (1u << TABLE_LOG2)
#define TABLE_MASK (TABLE_SIZE - 1u)

// Scratch (allocation-free): hash table keys + values.
__device__ int g_keys[TABLE_SIZE];
__device__ int g_vals[TABLE_SIZE];

__device__ __forceinline__ uint32_t hash_key(int key) {
    // Fibonacci hashing; keys are < 1e8, well mixed into TABLE_LOG2 bits.
    return (uint32_t(key) * 0x9E3779B1u) >> (32 - TABLE_LOG2);
}

// Kernel 1: reset table. int4-vectorized: 4 slots per thread per array.
__global__ void reset_table_kernel() {
    uint32_t i = blockIdx.x * blockDim.x + threadIdx.x;
    int4 neg = make_int4(-1, -1, -1, -1);
    if (i < TABLE_SIZE / 4) {
        reinterpret_cast<int4*>(g_keys)[i] = neg;
        reinterpret_cast<int4*>(g_vals)[i] = neg;
    }
}

// Kernel 2: insert old edges. Duplicate keys -> max index wins.
__global__ void insert_kernel(const int* __restrict__ edge_index_old,
                              int E_old, int total_nodes) {
    int i = blockIdx.x * blockDim.x + threadIdx.x;
    if (i >= E_old) return;
    int src = edge_index_old[i];
    int dst = edge_index_old[E_old + i];
    int key = src * total_nodes + dst;

    uint32_t h = hash_key(key);
    while (true) {
        int prev = atomicCAS(&g_keys[h], -1, key);
        if (prev == -1 || prev == key) {
            atomicMax(&g_vals[h], i);
            break;
        }
        h = (h + 1) & TABLE_MASK;
    }
}

// Kernel 3: lookup each new edge, gather old features, emit [E_new, 8].
__global__ void lookup_emit_kernel(const int*   __restrict__ edge_index_new,
                                   const float* __restrict__ edge_attr_old,
                                   const float* __restrict__ flow_old,
                                   const float* __restrict__ edge_attr_new,
                                   float*       __restrict__ out,
                                   int E_new, int total_nodes) {
    int i = blockIdx.x * blockDim.x + threadIdx.x;
    if (i >= E_new) return;
    int src = edge_index_new[i];
    int dst = edge_index_new[E_new + i];
    int key = src * total_nodes + dst;

    int match = -1;
    uint32_t h = hash_key(key);
    while (true) {
        int k = g_keys[h];
        if (k == key) { match = g_vals[h]; break; }
        if (k == -1)  { break; }
        h = (h + 1) & TABLE_MASK;
    }

    float a0 = 0.f, a1 = 0.f, a2 = 0.f, a3 = 0.f;
    float flag = 1.f;  // is_new_edge
    if (match >= 0) {
        const float* ea = edge_attr_old + (size_t)match * 3;
        a0 = __ldg(ea + 0);
        a1 = __ldg(ea + 1);
        a2 = __ldg(ea + 2);
        a3 = __ldg(flow_old + match);
        flag = 0.f;
    }
    const float* en = edge_attr_new + (size_t)i * 3;
    float n0 = en[0], n1 = en[1], n2 = en[2];

    float4* o = reinterpret_cast<float4*>(out + (size_t)i * 8);
    o[0] = make_float4(a0, a1, a2, a3);
    o[1] = make_float4(n0, n1, n2, flag);
}

extern "C" void kernel_launch(void* const* d_in, const int* in_sizes, int n_in,
                              void* d_out, int out_size) {
    const int*   edge_index_old = (const int*)  d_in[0];
    const float* edge_attr_old  = (const float*)d_in[1];
    const float* flow_old       = (const float*)d_in[2];
    const int*   edge_index_new = (const int*)  d_in[3];
    const float* edge_attr_new  = (const float*)d_in[4];
    (void)flow_old; (void)n_in;

    int E_old = in_sizes[1] / 3;   // edge_attr_old is [E_old, 3]
    int E_new = in_sizes[4] / 3;   // edge_attr_new is [E_new, 3]
    int total_nodes = 10000;       // fixed by problem; key fits int32

    float* out = (float*)d_out;
    (void)out_size;

    // 1) reset hash table
    {
        int threads = 256;
        int blocks = (TABLE_SIZE / 4 + threads - 1) / threads;
        reset_table_kernel<<<blocks, threads>>>();
    }
    // 2) insert old edges
    {
        int threads = 256;
        int blocks = (E_old + threads - 1) / threads;
        insert_kernel<<<blocks, threads>>>(edge_index_old, E_old, total_nodes);
    }
    // 3) lookup + emit
    {
        int threads = 256;
        int blocks = (E_new + threads - 1) / threads;
        lookup_emit_kernel<<<blocks, threads>>>(edge_index_new, edge_attr_old,
                                                (const float*)d_in[2],
                                                edge_attr_new, out,
                                                E_new, total_nodes);
    }
}

// round 4
// speedup vs baseline: 1.0155x; 1.0155x over previous
#include <cuda_runtime.h>
#include <cuda_bf16.h>
#include <cstdint>

// ---------------------------------------------------------------------------
// EdgeAlignmentModule: hash-join of new edges against old edges.
//   key(src,dst) = src * total_nodes + dst   (< 1e8, fits in uint32)
// Hash table slot = single uint64 word:  (old_edge_idx << 32) | key.
// Duplicate keys resolve to MAX old index (== sequential scatter "last wins"
// of table.at[old_keys].set(arange)) via atomicMax on the packed word
// (low 32 bits identical for equal keys, so max orders by index).
// ---------------------------------------------------------------------------

#define TABLE_LOG2 20
#define TABLE_SIZE (1u << TABLE_LOG2)
#define TABLE_MASK (TABLE_SIZE - 1u)
#define EMPTY_WORD 0xFFFFFFFFFFFFFFFFull

// Scratch (allocation-free): packed hash table.
__device__ unsigned long long g_tab[TABLE_SIZE];

__device__ __forceinline__ uint32_t hash_key(uint32_t key) {
    return (key * 0x9E3779B1u) >> (32 - TABLE_LOG2);
}

// Kernel 1: reset table to EMPTY. uint4-vectorized (2 slots / 16B per store).
__global__ void reset_table_kernel() {
    uint32_t i = blockIdx.x * blockDim.x + threadIdx.x;
    if (i < TABLE_SIZE / 2) {
        reinterpret_cast<uint4*>(g_tab)[i] =
            make_uint4(0xFFFFFFFFu, 0xFFFFFFFFu, 0xFFFFFFFFu, 0xFFFFFFFFu);
    }
}

// Kernel 2: insert old edges. One CAS claims slot+value; atomicMax only on
// genuine duplicate keys (~hundreds).
__global__ void insert_kernel(const int* __restrict__ edge_index_old,
                              int E_old, int total_nodes) {
    int i = blockIdx.x * blockDim.x + threadIdx.x;
    if (i >= E_old) return;
    uint32_t key = (uint32_t)(__ldg(edge_index_old + i) * total_nodes
                              + __ldg(edge_index_old + E_old + i));
    unsigned long long word = ((unsigned long long)(uint32_t)i << 32) | key;

    uint32_t h = hash_key(key);
    while (true) {
        unsigned long long prev = atomicCAS(&g_tab[h], EMPTY_WORD, word);
        if (prev == EMPTY_WORD) break;               // claimed slot + value
        if ((uint32_t)prev == key) {                 // same key: max idx wins
            atomicMax(&g_tab[h], word);
            break;
        }
        h = (h + 1) & TABLE_MASK;
    }
}

// Kernel 3: lookup each new edge, gather old features, emit [E_new, 8].
__global__ void lookup_emit_kernel(const int*   __restrict__ edge_index_new,
                                   const float* __restrict__ edge_attr_old,
                                   const float* __restrict__ flow_old,
                                   const float* __restrict__ edge_attr_new,
                                   float*       __restrict__ out,
                                   int E_new, int total_nodes) {
    int i = blockIdx.x * blockDim.x + threadIdx.x;
    if (i >= E_new) return;
    uint32_t key = (uint32_t)(__ldg(edge_index_new + i) * total_nodes
                              + __ldg(edge_index_new + E_new + i));

    int match = -1;
    uint32_t h = hash_key(key);
    while (true) {
        unsigned long long w = __ldg(&g_tab[h]);
        if ((uint32_t)w == key) { match = (int)(w >> 32); break; }
        if (w == EMPTY_WORD)    { break; }
        h = (h + 1) & TABLE_MASK;
    }

    float a0 = 0.f, a1 = 0.f, a2 = 0.f, a3 = 0.f;
    float flag = 1.f;  // is_new_edge
    if (match >= 0) {
        const float* ea = edge_attr_old + (size_t)match * 3;
        a0 = __ldg(ea + 0);
        a1 = __ldg(ea + 1);
        a2 = __ldg(ea + 2);
        a3 = __ldg(flow_old + match);
        flag = 0.f;
    }
    const float* en = edge_attr_new + (size_t)i * 3;
    float n0 = __ldg(en + 0), n1 = __ldg(en + 1), n2 = __ldg(en + 2);

    float4* o = reinterpret_cast<float4*>(out + (size_t)i * 8);
    o[0] = make_float4(a0, a1, a2, a3);
    o[1] = make_float4(n0, n1, n2, flag);
}

extern "C" void kernel_launch(void* const* d_in, const int* in_sizes, int n_in,
                              void* d_out, int out_size) {
    const int*   edge_index_old = (const int*)  d_in[0];
    const float* edge_attr_old  = (const float*)d_in[1];
    const float* flow_old       = (const float*)d_in[2];
    const int*   edge_index_new = (const int*)  d_in[3];
    const float* edge_attr_new  = (const float*)d_in[4];
    (void)n_in; (void)out_size;

    int E_old = in_sizes[1] / 3;   // edge_attr_old is [E_old, 3]
    int E_new = in_sizes[4] / 3;   // edge_attr_new is [E_new, 3]
    int total_nodes = 10000;       // fixed by problem; key fits uint32

    float* out = (float*)d_out;

    {   // 1) reset hash table (8 MB)
        int threads = 256;
        int blocks = (TABLE_SIZE / 2 + threads - 1) / threads;
        reset_table_kernel<<<blocks, threads>>>();
    }
    {   // 2) insert old edges
        int threads = 256;
        int blocks = (E_old + threads - 1) / threads;
        insert_kernel<<<blocks, threads>>>(edge_index_old, E_old, total_nodes);
    }
    {   // 3) lookup + emit
        int threads = 256;
        int blocks = (E_new + threads - 1) / threads;
        lookup_emit_kernel<<<blocks, threads>>>(edge_index_new, edge_attr_old,
                                                flow_old, edge_attr_new, out,
                                                E_new, total_nodes);
    }
}